// round 14
// baseline (speedup 1.0000x reference)
#include <cuda_runtime.h>
#include <cuda_fp16.h>

// Problem constants
namespace {
constexpr int B  = 4;
constexpr int S  = 1024;
constexpr int DM = 512;
constexpr int DA = 512;
constexpr int H  = 8;
constexpr int F  = 16;
}

// Scratch (static device globals -- no allocations allowed)
__device__ float  g_qp [B * S * DA];      // 8 MB (tf32-rounded)
__device__ float  g_kp [B * S * DA];      // 8 MB (tf32-rounded)
__device__ float  g_vp [B * S * DA];      // 8 MB (tf32-rounded)
__device__ float  g_x  [B * S * H * F];   // 2 MB
__device__ float  g_ctx[B * S * DA];      // 8 MB
__device__ __half g_bias[(size_t)B * H * S * S];  // 64 MB (fp16 logit bias)

// ---------------------------------------------------------------------------
// tf32 / cp.async helpers
// ---------------------------------------------------------------------------
__device__ __forceinline__ unsigned f2tf(float f) {
    unsigned u;
    asm("cvt.rna.tf32.f32 %0, %1;" : "=r"(u) : "f"(f));
    return u;
}

__device__ __forceinline__ void mma_tf32(float c[4],
                                         unsigned a0, unsigned a1, unsigned a2, unsigned a3,
                                         unsigned b0, unsigned b1) {
    asm volatile(
        "mma.sync.aligned.m16n8k8.row.col.f32.tf32.tf32.f32 "
        "{%0,%1,%2,%3}, {%4,%5,%6,%7}, {%8,%9}, {%0,%1,%2,%3};"
        : "+f"(c[0]), "+f"(c[1]), "+f"(c[2]), "+f"(c[3])
        : "r"(a0), "r"(a1), "r"(a2), "r"(a3), "r"(b0), "r"(b1));
}

__device__ __forceinline__ void cp16(void* dst_smem, const void* src_gmem) {
    const unsigned s = (unsigned)__cvta_generic_to_shared(dst_smem);
    asm volatile("cp.async.cg.shared.global [%0], [%1], 16;" :: "r"(s), "l"(src_gmem));
}
#define CP_COMMIT() asm volatile("cp.async.commit_group;")
#define CP_WAIT0()  asm volatile("cp.async.wait_group 0;" ::: "memory")

// ---------------------------------------------------------------------------
// 64x64-tile tf32 GEMM body: C[m0:64, n0:64] = A[M,K] @ W[K,N] + bias
// 128 threads (4 warps, warp-tile 32x32), BK=16, reg-prefetch double buffer.
// TF32OUT: round stored output to tf32 (for q/k/v projections).
// ---------------------------------------------------------------------------
template <bool TF32OUT>
__device__ __forceinline__ void gemm64_body(
    const float* __restrict__ A, const float* __restrict__ W,
    const float* __restrict__ bias, float* __restrict__ C,
    int N, int K, int m0, int n0)
{
    constexpr int AS = 20;   // As[m][k], 16+4
    constexpr int BS = 72;   // Bs[k][n], 64+8
    __shared__ unsigned As[64 * AS];
    __shared__ unsigned Bs[16 * BS];

    const int tid  = threadIdx.x;
    const int warp = tid >> 5;
    const int lane = tid & 31;
    const int gid  = lane >> 2;
    const int tig  = lane & 3;
    const int wm   = (warp & 1) * 32;
    const int wn   = (warp >> 1) * 32;

    float4 ra[2], rb[2];
#pragma unroll
    for (int p = 0; p < 2; p++) {
        const int ia = tid + p * 128;
        ra[p] = *(const float4*)&A[(size_t)(m0 + (ia >> 2)) * K + (ia & 3) * 4];
        const int ib = tid + p * 128;
        rb[p] = *(const float4*)&W[(size_t)(ib >> 4) * N + n0 + (ib & 15) * 4];
    }

    float acc[2][4][4] = {};

    for (int k0 = 0; k0 < K; k0 += 16) {
#pragma unroll
        for (int p = 0; p < 2; p++) {
            const int ia = tid + p * 128;
            unsigned* pa = &As[(ia >> 2) * AS + (ia & 3) * 4];
            pa[0] = f2tf(ra[p].x); pa[1] = f2tf(ra[p].y);
            pa[2] = f2tf(ra[p].z); pa[3] = f2tf(ra[p].w);
            const int ib = tid + p * 128;
            unsigned* pb = &Bs[(ib >> 4) * BS + (ib & 15) * 4];
            pb[0] = f2tf(rb[p].x); pb[1] = f2tf(rb[p].y);
            pb[2] = f2tf(rb[p].z); pb[3] = f2tf(rb[p].w);
        }
        __syncthreads();
        if (k0 + 16 < K) {
#pragma unroll
            for (int p = 0; p < 2; p++) {
                const int ia = tid + p * 128;
                ra[p] = *(const float4*)&A[(size_t)(m0 + (ia >> 2)) * K + k0 + 16 + (ia & 3) * 4];
                const int ib = tid + p * 128;
                rb[p] = *(const float4*)&W[(size_t)(k0 + 16 + (ib >> 4)) * N + n0 + (ib & 15) * 4];
            }
        }
#pragma unroll
        for (int ks = 0; ks < 2; ks++) {
            unsigned afr[2][4];
#pragma unroll
            for (int mi = 0; mi < 2; mi++) {
                const int mr = wm + mi * 16 + gid;
                afr[mi][0] = As[mr * AS + ks * 8 + tig];
                afr[mi][1] = As[(mr + 8) * AS + ks * 8 + tig];
                afr[mi][2] = As[mr * AS + ks * 8 + tig + 4];
                afr[mi][3] = As[(mr + 8) * AS + ks * 8 + tig + 4];
            }
            unsigned bfr[4][2];
#pragma unroll
            for (int ni = 0; ni < 4; ni++) {
                const int nc = wn + ni * 8 + gid;
                bfr[ni][0] = Bs[(ks * 8 + tig) * BS + nc];
                bfr[ni][1] = Bs[(ks * 8 + tig + 4) * BS + nc];
            }
#pragma unroll
            for (int mi = 0; mi < 2; mi++)
#pragma unroll
                for (int ni = 0; ni < 4; ni++)
                    mma_tf32(acc[mi][ni], afr[mi][0], afr[mi][1], afr[mi][2], afr[mi][3],
                             bfr[ni][0], bfr[ni][1]);
        }
        __syncthreads();
    }

#pragma unroll
    for (int mi = 0; mi < 2; mi++) {
        const int row = m0 + wm + mi * 16 + gid;
#pragma unroll
        for (int ni = 0; ni < 4; ni++) {
            const int col = n0 + wn + ni * 8 + 2 * tig;
            const float2 bb = *(const float2*)&bias[col];
            float2 o0, o1;
            o0.x = acc[mi][ni][0] + bb.x; o0.y = acc[mi][ni][1] + bb.y;
            o1.x = acc[mi][ni][2] + bb.x; o1.y = acc[mi][ni][3] + bb.y;
            if (TF32OUT) {
                o0.x = __uint_as_float(f2tf(o0.x)); o0.y = __uint_as_float(f2tf(o0.y));
                o1.x = __uint_as_float(f2tf(o1.x)); o1.y = __uint_as_float(f2tf(o1.y));
            }
            *(float2*)&C[(size_t)row * N + col]       = o0;
            *(float2*)&C[(size_t)(row + 8) * N + col] = o1;
        }
    }
}

// q/k/v projections batched over blockIdx.z (tf32-rounded outputs)
__global__ __launch_bounds__(128) void qkv_proj_kernel(
    const float* __restrict__ q, const float* __restrict__ k, const float* __restrict__ v,
    const float* __restrict__ Wq, const float* __restrict__ bq,
    const float* __restrict__ Wk, const float* __restrict__ bk,
    const float* __restrict__ Wv, const float* __restrict__ bv,
    float* __restrict__ qp, float* __restrict__ kp, float* __restrict__ vp)
{
    const int z = blockIdx.z;
    const float* A    = (z == 0) ? q  : (z == 1) ? k  : v;
    const float* W    = (z == 0) ? Wq : (z == 1) ? Wk : Wv;
    const float* bias = (z == 0) ? bq : (z == 1) ? bk : bv;
    float*       C    = (z == 0) ? qp : (z == 1) ? kp : vp;
    gemm64_body<true>(A, W, bias, C, DA, DM, blockIdx.y * 64, blockIdx.x * 64);
}

// generic single GEMM (x projection, output projection)
__global__ __launch_bounds__(128) void gemm64_kernel(
    const float* __restrict__ A, const float* __restrict__ W,
    const float* __restrict__ bias, float* __restrict__ C, int N, int K)
{
    gemm64_body<false>(A, W, bias, C, N, K, blockIdx.y * 64, blockIdx.x * 64);
}

// ---------------------------------------------------------------------------
// xdiff bias (fp16 out): bias[b,h,q,k] = 0.5 * sum_f xdiff[b,q,k,f]*x[b,q,h*F+f]
// One CTA per (b,q); each thread handles 2 adjacent k -> half2 stores.
// xdiff is streamed with evict-first (read exactly once).
// ---------------------------------------------------------------------------
__global__ __launch_bounds__(256) void xbias_kernel(
    const float* __restrict__ xdiff, const float* __restrict__ xg,
    __half* __restrict__ bias)
{
    __shared__ float xh[H * F];
    const int bq  = blockIdx.x;
    const int b   = bq >> 10;
    const int qi  = bq & 1023;
    const int tid = threadIdx.x;
    if (tid < H * F) xh[tid] = xg[(size_t)bq * (H * F) + tid];
    __syncthreads();
    const float* xd = xdiff + (size_t)bq * S * F;
#pragma unroll
    for (int kt = 0; kt < 2; kt++) {
        const int k = kt * 512 + tid * 2;
        float xv[2][16];
#pragma unroll
        for (int r = 0; r < 2; r++) {
            const float4* src = (const float4*)&xd[(size_t)(k + r) * F];
            const float4 t0 = __ldcs(src + 0);
            const float4 t1 = __ldcs(src + 1);
            const float4 t2 = __ldcs(src + 2);
            const float4 t3 = __ldcs(src + 3);
            xv[r][0]  = t0.x; xv[r][1]  = t0.y; xv[r][2]  = t0.z; xv[r][3]  = t0.w;
            xv[r][4]  = t1.x; xv[r][5]  = t1.y; xv[r][6]  = t1.z; xv[r][7]  = t1.w;
            xv[r][8]  = t2.x; xv[r][9]  = t2.y; xv[r][10] = t2.z; xv[r][11] = t2.w;
            xv[r][12] = t3.x; xv[r][13] = t3.y; xv[r][14] = t3.z; xv[r][15] = t3.w;
        }
#pragma unroll
        for (int h = 0; h < H; h++) {
            float s0 = 0.0f, s1 = 0.0f;
#pragma unroll
            for (int f = 0; f < F; f++) {
                const float w = xh[h * F + f];
                s0 = fmaf(xv[0][f], w, s0);
                s1 = fmaf(xv[1][f], w, s1);
            }
            const __half2 hv = __floats2half2_rn(0.5f * s0, 0.5f * s1);
            *(__half2*)&bias[((size_t)(b * H + h) * S + qi) * S + k] = hv;
        }
    }
}

// ---------------------------------------------------------------------------
// Fused attention, 512 threads / 16 warps, cp.async double-buffered chunks.
// Inputs qp/kp/vp are tf32-pre-rounded -> staging is a pure 16B cp.async copy.
// Bias is fp16 (64MB; mostly L2-resident after xbias).
//   acc = bias (prefetched half2 LDG) + QK^T (Q frags hoisted) -> STS to L
//   softmax(L float) -> attn gmem (float, evict-first) + L (tf32 bits)
//   PV: q(2) x d-half(2x32col) x ks-quarter(4) split; 4-way partial reduce.
//   V chunks 0/1 prefetched during QK tail + softmax.
// smem: L 32x1044 + Qs 32x68 + 2 x (128x72 KV buffers) = 216,064 B
// ---------------------------------------------------------------------------
namespace {
constexpr int LSTR = 1044;
constexpr int QSTR = 68;
constexpr int KSTK = 68;   // K-phase layout stride inside buffer
constexpr int KSTV = 72;   // V-phase layout stride
constexpr int BUFW = 128 * KSTV;
constexpr int PSTR = 72;   // partial-reduce scratch stride
constexpr int FATTN_SMEM = (32 * LSTR + 32 * QSTR + 2 * BUFW) * 4;
}

__global__ __launch_bounds__(512) void fattn_kernel(
    const float* __restrict__ qp, const float* __restrict__ kp,
    const float* __restrict__ vp, const __half* __restrict__ biash,
    float* __restrict__ attn, float* __restrict__ ctx)
{
    extern __shared__ float smem[];
    float*    L  = smem;                               // 32 x LSTR (float / tf32 bits)
    unsigned* Lu = (unsigned*)smem;
    unsigned* Qs = (unsigned*)(smem + 32 * LSTR);      // 32 x QSTR
    unsigned* KV = Qs + 32 * QSTR;                     // 2 x BUFW

    const int tid  = threadIdx.x;
    const int warp = tid >> 5;          // 0..15
    const int lane = tid & 31;
    const int gid  = lane >> 2;
    const int tig  = lane & 3;

    const int bh = blockIdx.y;           // b*H + h
    const int b  = bh >> 3;
    const int h  = bh & 7;
    const int q0 = blockIdx.x * 32;

    const size_t bh_row0 = ((size_t)bh * S + q0) * S;

    const float* Kb = kp + (size_t)b * S * DA + h * 64;
    const float* Vb = vp + (size_t)b * S * DA + h * 64;
    // bias tile as half2 rows: [q][k/2]
    const __half2* Bq = (const __half2*)(biash + (size_t)bh * S * S) + (size_t)q0 * (S / 2);

    // ---- issue cp.async for K chunk 0 ----
#pragma unroll
    for (int p = 0; p < 4; p++) {
        const int i = tid + p * 512;
        cp16(&KV[(i >> 4) * KSTK + (i & 15) * 4], &Kb[(size_t)(i >> 4) * DA + (i & 15) * 4]);
    }
    CP_COMMIT();

    // ---- Q tile -> Qs (x0.125 exact; values already tf32-rounded) ----
    {
        const int row = tid >> 4;
        const int c4  = (tid & 15) * 4;
        const float4 v = *(const float4*)&qp[(size_t)(b * S + q0 + row) * DA + h * 64 + c4];
        unsigned* p = &Qs[row * QSTR + c4];
        p[0] = __float_as_uint(v.x * 0.125f); p[1] = __float_as_uint(v.y * 0.125f);
        p[2] = __float_as_uint(v.z * 0.125f); p[3] = __float_as_uint(v.w * 0.125f);
    }

    // ---- prefetch bias for chunk 0 (half2: one pair per row-group) ----
    const int cidx = warp * 4 + tig;           // half2 index of this warp's col pair
    __half2 bp[2][2];
#pragma unroll
    for (int mi = 0; mi < 2; mi++) {
        const int row = mi * 16 + gid;
        bp[mi][0] = Bq[(size_t)row * (S / 2) + cidx];
        bp[mi][1] = Bq[(size_t)(row + 8) * (S / 2) + cidx];
    }
    CP_WAIT0();
    __syncthreads();

    // ---- hoist Q fragments into registers ----
    unsigned qa[2][8][4];
#pragma unroll
    for (int mi = 0; mi < 2; mi++) {
        const int mr = mi * 16 + gid;
#pragma unroll
        for (int ks = 0; ks < 8; ks++) {
            qa[mi][ks][0] = Qs[mr * QSTR + ks * 8 + tig];
            qa[mi][ks][1] = Qs[(mr + 8) * QSTR + ks * 8 + tig];
            qa[mi][ks][2] = Qs[mr * QSTR + ks * 8 + tig + 4];
            qa[mi][ks][3] = Qs[(mr + 8) * QSTR + ks * 8 + tig + 4];
        }
    }

    const int colw = warp * 8 + tig * 2;       // this warp's 8 cols within a chunk

    // ---- QK^T: acc = bias + QK; result stored once to L ----
    for (int kt = 0; kt < 8; kt++) {
        const unsigned* cur = KV + (kt & 1) * BUFW;

        if (kt < 7) {
            unsigned* nxt = KV + ((kt + 1) & 1) * BUFW;
            const int kbase = (kt + 1) * 128;
#pragma unroll
            for (int p = 0; p < 4; p++) {
                const int i = tid + p * 512;
                cp16(&nxt[(i >> 4) * KSTK + (i & 15) * 4],
                     &Kb[(size_t)(kbase + (i >> 4)) * DA + (i & 15) * 4]);
            }
            CP_COMMIT();
        } else {
            // last K chunk: prefetch V chunk 0 into the other buffer (buf0)
            unsigned* nxt = KV;    // buffer 0
#pragma unroll
            for (int p = 0; p < 4; p++) {
                const int i = tid + p * 512;
                cp16(&nxt[(i >> 4) * KSTV + (i & 15) * 4],
                     &Vb[(size_t)(i >> 4) * DA + (i & 15) * 4]);
            }
            CP_COMMIT();
        }

        float acc[2][4];
#pragma unroll
        for (int mi = 0; mi < 2; mi++) {
            const float2 t0 = __half22float2(bp[mi][0]);
            const float2 t1 = __half22float2(bp[mi][1]);
            acc[mi][0] = t0.x; acc[mi][1] = t0.y; acc[mi][2] = t1.x; acc[mi][3] = t1.y;
        }

        // prefetch bias for next chunk (overlaps mma loop)
        if (kt < 7) {
            const int nci = (kt + 1) * 64 + cidx;
#pragma unroll
            for (int mi = 0; mi < 2; mi++) {
                const int row = mi * 16 + gid;
                bp[mi][0] = Bq[(size_t)row * (S / 2) + nci];
                bp[mi][1] = Bq[(size_t)(row + 8) * (S / 2) + nci];
            }
        }

#pragma unroll
        for (int ks = 0; ks < 8; ks++) {
            const int nc = warp * 8 + gid;
            const unsigned b0 = cur[nc * KSTK + ks * 8 + tig];
            const unsigned b1 = cur[nc * KSTK + ks * 8 + tig + 4];
            mma_tf32(acc[0], qa[0][ks][0], qa[0][ks][1], qa[0][ks][2], qa[0][ks][3], b0, b1);
            mma_tf32(acc[1], qa[1][ks][0], qa[1][ks][1], qa[1][ks][2], qa[1][ks][3], b0, b1);
        }

        // store logits tile (single write, no RMW)
        const int colb = kt * 128 + colw;
#pragma unroll
        for (int mi = 0; mi < 2; mi++) {
            const int row = mi * 16 + gid;
            *(float2*)&L[row * LSTR + colb]       = make_float2(acc[mi][0], acc[mi][1]);
            *(float2*)&L[(row + 8) * LSTR + colb] = make_float2(acc[mi][2], acc[mi][3]);
        }
        if (kt < 7) CP_WAIT0();
        __syncthreads();
    }

    // ---- issue cp.async for V chunk 1 (buf1 free now; overlaps softmax) ----
    {
        unsigned* nxt = KV + BUFW;   // buffer 1
#pragma unroll
        for (int p = 0; p < 4; p++) {
            const int i = tid + p * 512;
            cp16(&nxt[(i >> 4) * KSTV + (i & 15) * 4],
                 &Vb[(size_t)(128 + (i >> 4)) * DA + (i & 15) * 4]);
        }
        CP_COMMIT();
    }

    // ---- softmax (warp per 2 rows): attn gmem (float, evict-first) + L (tf32) ----
#pragma unroll
    for (int r = 0; r < 2; r++) {
        const int row = warp * 2 + r;
        float* Lr = &L[row * LSTR];
        float4 v[8];
        float m = -1e30f;
#pragma unroll
        for (int c = 0; c < 8; c++) {
            v[c] = *(float4*)&Lr[c * 128 + lane * 4];
            m = fmaxf(m, fmaxf(fmaxf(v[c].x, v[c].y), fmaxf(v[c].z, v[c].w)));
        }
#pragma unroll
        for (int o = 16; o; o >>= 1) m = fmaxf(m, __shfl_xor_sync(0xffffffffu, m, o));
        float s = 0.0f;
#pragma unroll
        for (int c = 0; c < 8; c++) {
            v[c].x = __expf(v[c].x - m); v[c].y = __expf(v[c].y - m);
            v[c].z = __expf(v[c].z - m); v[c].w = __expf(v[c].w - m);
            s += v[c].x + v[c].y + v[c].z + v[c].w;
        }
#pragma unroll
        for (int o = 16; o; o >>= 1) s += __shfl_xor_sync(0xffffffffu, s, o);
        const float inv = 1.0f / s;
        float* Ar = attn + bh_row0 + (size_t)row * S;
#pragma unroll
        for (int c = 0; c < 8; c++) {
            v[c].x *= inv; v[c].y *= inv; v[c].z *= inv; v[c].w *= inv;
            __stcs((float4*)&Ar[c * 128 + lane * 4], v[c]);
            uint4 u;
            u.x = f2tf(v[c].x); u.y = f2tf(v[c].y);
            u.z = f2tf(v[c].z); u.w = f2tf(v[c].w);
            *(uint4*)&Lu[row * LSTR + c * 128 + lane * 4] = u;
        }
    }
    CP_WAIT0();
    __syncthreads();

    // ---- PV: ctx tile [32,64] = L @ V ----
    // warp = (wg: ks-quarter) x (mi: q half) x (wn: d half of 32 cols)
    const int wg  = warp >> 2;          // 0..3: which quarter of each chunk's k8-steps
    const int sub = warp & 3;
    const int mi  = sub & 1;
    const int wn  = (sub >> 1) * 32;    // 32 d-cols per warp (4 mma per A-frag)
    const int row = mi * 16 + gid;
    float pacc[4][4] = {};
    for (int kt = 0; kt < 8; kt++) {
        const unsigned* cur = KV + (kt & 1) * BUFW;
        if (kt >= 1 && kt < 7) {
            unsigned* nxt = KV + ((kt + 1) & 1) * BUFW;
            const int kbase = (kt + 1) * 128;
#pragma unroll
            for (int p = 0; p < 4; p++) {
                const int i = tid + p * 512;
                cp16(&nxt[(i >> 4) * KSTV + (i & 15) * 4],
                     &Vb[(size_t)(kbase + (i >> 4)) * DA + (i & 15) * 4]);
            }
            CP_COMMIT();
        }

#pragma unroll
        for (int ks = 0; ks < 4; ks++) {
            const int ksc = wg * 4 + ks;              // 0..15 k8-steps of this chunk
            const int kk  = kt * 128 + ksc * 8;
            const unsigned a0 = Lu[row * LSTR + kk + tig];
            const unsigned a1 = Lu[(row + 8) * LSTR + kk + tig];
            const unsigned a2 = Lu[row * LSTR + kk + tig + 4];
            const unsigned a3 = Lu[(row + 8) * LSTR + kk + tig + 4];
#pragma unroll
            for (int ni = 0; ni < 4; ni++) {
                const unsigned b0 = cur[(ksc * 8 + tig) * KSTV + wn + ni * 8 + gid];
                const unsigned b1 = cur[(ksc * 8 + tig + 4) * KSTV + wn + ni * 8 + gid];
                mma_tf32(pacc[ni], a0, a1, a2, a3, b0, b1);
            }
        }
        if (kt < 7) CP_WAIT0();
        __syncthreads();
    }

    // ---- 4-way partial reduction through freed KV smem, then store ctx ----
    float* Pp = (float*)KV;             // scratch: 3 regions of 32 x PSTR
    if (wg != 0) {
        const int base = (wg - 1) * (32 * PSTR);
#pragma unroll
        for (int ni = 0; ni < 4; ni++) {
            const int col = wn + ni * 8 + tig * 2;
            *(float2*)&Pp[base + row * PSTR + col]       = make_float2(pacc[ni][0], pacc[ni][1]);
            *(float2*)&Pp[base + (row + 8) * PSTR + col] = make_float2(pacc[ni][2], pacc[ni][3]);
        }
    }
    __syncthreads();
    if (wg == 0) {
        const int grow = b * S + q0 + row;
#pragma unroll
        for (int ni = 0; ni < 4; ni++) {
            const int col = wn + ni * 8 + tig * 2;
            float2 o0 = make_float2(pacc[ni][0], pacc[ni][1]);
            float2 o1 = make_float2(pacc[ni][2], pacc[ni][3]);
#pragma unroll
            for (int r = 0; r < 3; r++) {
                const int base = r * (32 * PSTR);
                const float2 p0 = *(const float2*)&Pp[base + row * PSTR + col];
                const float2 p1 = *(const float2*)&Pp[base + (row + 8) * PSTR + col];
                o0.x += p0.x; o0.y += p0.y;
                o1.x += p1.x; o1.y += p1.y;
            }
            *(float2*)&ctx[(size_t)grow * DA + h * 64 + col]       = o0;
            *(float2*)&ctx[(size_t)(grow + 8) * DA + h * 64 + col] = o1;
        }
    }
}

// ---------------------------------------------------------------------------
extern "C" void kernel_launch(void* const* d_in, const int* in_sizes, int n_in,
                              void* d_out, int out_size)
{
    const float* q     = (const float*)d_in[0];
    const float* k     = (const float*)d_in[1];
    const float* v     = (const float*)d_in[2];
    const float* xdiff = (const float*)d_in[3];
    const float* Wq    = (const float*)d_in[4];
    const float* bq    = (const float*)d_in[5];
    const float* Wk    = (const float*)d_in[6];
    const float* bk    = (const float*)d_in[7];
    const float* Wv    = (const float*)d_in[8];
    const float* bv    = (const float*)d_in[9];
    const float* Wx    = (const float*)d_in[10];
    const float* bx    = (const float*)d_in[11];
    const float* Wo    = (const float*)d_in[12];
    const float* bo    = (const float*)d_in[13];

    float* out_final = (float*)d_out;                       // [B,S,DM]
    float* attn      = out_final + (size_t)B * S * DM;      // [B,H,S,S]

    float *qp, *kp, *vp, *xg, *ctx;
    __half* biasb;
    cudaGetSymbolAddress((void**)&qp,    g_qp);
    cudaGetSymbolAddress((void**)&kp,    g_kp);
    cudaGetSymbolAddress((void**)&vp,    g_vp);
    cudaGetSymbolAddress((void**)&xg,    g_x);
    cudaGetSymbolAddress((void**)&ctx,   g_ctx);
    cudaGetSymbolAddress((void**)&biasb, g_bias);

    cudaFuncSetAttribute(fattn_kernel, cudaFuncAttributeMaxDynamicSharedMemorySize,
                         FATTN_SMEM);

    // 1. q/k/v projections, one batched launch (tf32-rounded outputs)
    qkv_proj_kernel<<<dim3(DA / 64, (B * S) / 64, 3), 128>>>(
        q, k, v, Wq, bq, Wk, bk, Wv, bv, qp, kp, vp);

    // 2. x = qp @ Wx + bx
    gemm64_kernel<<<dim3((H * F) / 64, (B * S) / 64), 128>>>(qp, Wx, bx, xg, H * F, DA);

    // 3. xdiff relative bias -> fp16 bias buffer
    xbias_kernel<<<B * S, 256>>>(xdiff, xg, biasb);

    // 4. fused: logits = bias + QK^T, softmax, attn out, PV -> ctx
    fattn_kernel<<<dim3(S / 32, B * H), 512, FATTN_SMEM>>>(qp, kp, vp, biasb, attn, ctx);

    // 5. output = ctx @ Wo + bo
    gemm64_kernel<<<dim3(DM / 64, (B * S) / 64), 128>>>(ctx, Wo, bo, out_final, DM, DA);
}

// round 15
// speedup vs baseline: 1.1643x; 1.1643x over previous
#include <cuda_runtime.h>
#include <cuda_fp16.h>

// Problem constants
namespace {
constexpr int B  = 4;
constexpr int S  = 1024;
constexpr int DM = 512;
constexpr int DA = 512;
constexpr int H  = 8;
constexpr int F  = 16;
}

// Scratch (static device globals -- no allocations allowed)
__device__ float  g_qp [B * S * DA];      // 8 MB (tf32-rounded)
__device__ float  g_kp [B * S * DA];      // 8 MB (tf32-rounded)
__device__ float  g_vp [B * S * DA];      // 8 MB (tf32-rounded)
__device__ float  g_x  [B * S * H * F];   // 2 MB
__device__ float  g_ctx[B * S * DA];      // 8 MB
__device__ __half g_bias[(size_t)B * H * S * S];  // 64 MB (fp16 logit bias)

// ---------------------------------------------------------------------------
// tf32 / cp.async helpers
// ---------------------------------------------------------------------------
__device__ __forceinline__ unsigned f2tf(float f) {
    unsigned u;
    asm("cvt.rna.tf32.f32 %0, %1;" : "=r"(u) : "f"(f));
    return u;
}

__device__ __forceinline__ void mma_tf32(float c[4],
                                         unsigned a0, unsigned a1, unsigned a2, unsigned a3,
                                         unsigned b0, unsigned b1) {
    asm volatile(
        "mma.sync.aligned.m16n8k8.row.col.f32.tf32.tf32.f32 "
        "{%0,%1,%2,%3}, {%4,%5,%6,%7}, {%8,%9}, {%0,%1,%2,%3};"
        : "+f"(c[0]), "+f"(c[1]), "+f"(c[2]), "+f"(c[3])
        : "r"(a0), "r"(a1), "r"(a2), "r"(a3), "r"(b0), "r"(b1));
}

__device__ __forceinline__ void cp16(void* dst_smem, const void* src_gmem) {
    const unsigned s = (unsigned)__cvta_generic_to_shared(dst_smem);
    asm volatile("cp.async.cg.shared.global [%0], [%1], 16;" :: "r"(s), "l"(src_gmem));
}
#define CP_COMMIT() asm volatile("cp.async.commit_group;")
#define CP_WAIT0()  asm volatile("cp.async.wait_group 0;" ::: "memory")

// ---------------------------------------------------------------------------
// 64x64-tile tf32 GEMM body: C[m0:64, n0:64] = A[M,K] @ W[K,N] + bias
// 128 threads (4 warps, warp-tile 32x32), BK=16, reg-prefetch double buffer.
// TF32OUT: round stored output to tf32 (for q/k/v projections).
// ---------------------------------------------------------------------------
template <bool TF32OUT>
__device__ __forceinline__ void gemm64_body(
    const float* __restrict__ A, const float* __restrict__ W,
    const float* __restrict__ bias, float* __restrict__ C,
    int N, int K, int m0, int n0)
{
    constexpr int AS = 20;   // As[m][k], 16+4
    constexpr int BS = 72;   // Bs[k][n], 64+8
    __shared__ unsigned As[64 * AS];
    __shared__ unsigned Bs[16 * BS];

    const int tid  = threadIdx.x;
    const int warp = tid >> 5;
    const int lane = tid & 31;
    const int gid  = lane >> 2;
    const int tig  = lane & 3;
    const int wm   = (warp & 1) * 32;
    const int wn   = (warp >> 1) * 32;

    float4 ra[2], rb[2];
#pragma unroll
    for (int p = 0; p < 2; p++) {
        const int ia = tid + p * 128;
        ra[p] = *(const float4*)&A[(size_t)(m0 + (ia >> 2)) * K + (ia & 3) * 4];
        const int ib = tid + p * 128;
        rb[p] = *(const float4*)&W[(size_t)(ib >> 4) * N + n0 + (ib & 15) * 4];
    }

    float acc[2][4][4] = {};

    for (int k0 = 0; k0 < K; k0 += 16) {
#pragma unroll
        for (int p = 0; p < 2; p++) {
            const int ia = tid + p * 128;
            unsigned* pa = &As[(ia >> 2) * AS + (ia & 3) * 4];
            pa[0] = f2tf(ra[p].x); pa[1] = f2tf(ra[p].y);
            pa[2] = f2tf(ra[p].z); pa[3] = f2tf(ra[p].w);
            const int ib = tid + p * 128;
            unsigned* pb = &Bs[(ib >> 4) * BS + (ib & 15) * 4];
            pb[0] = f2tf(rb[p].x); pb[1] = f2tf(rb[p].y);
            pb[2] = f2tf(rb[p].z); pb[3] = f2tf(rb[p].w);
        }
        __syncthreads();
        if (k0 + 16 < K) {
#pragma unroll
            for (int p = 0; p < 2; p++) {
                const int ia = tid + p * 128;
                ra[p] = *(const float4*)&A[(size_t)(m0 + (ia >> 2)) * K + k0 + 16 + (ia & 3) * 4];
                const int ib = tid + p * 128;
                rb[p] = *(const float4*)&W[(size_t)(k0 + 16 + (ib >> 4)) * N + n0 + (ib & 15) * 4];
            }
        }
#pragma unroll
        for (int ks = 0; ks < 2; ks++) {
            unsigned afr[2][4];
#pragma unroll
            for (int mi = 0; mi < 2; mi++) {
                const int mr = wm + mi * 16 + gid;
                afr[mi][0] = As[mr * AS + ks * 8 + tig];
                afr[mi][1] = As[(mr + 8) * AS + ks * 8 + tig];
                afr[mi][2] = As[mr * AS + ks * 8 + tig + 4];
                afr[mi][3] = As[(mr + 8) * AS + ks * 8 + tig + 4];
            }
            unsigned bfr[4][2];
#pragma unroll
            for (int ni = 0; ni < 4; ni++) {
                const int nc = wn + ni * 8 + gid;
                bfr[ni][0] = Bs[(ks * 8 + tig) * BS + nc];
                bfr[ni][1] = Bs[(ks * 8 + tig + 4) * BS + nc];
            }
#pragma unroll
            for (int mi = 0; mi < 2; mi++)
#pragma unroll
                for (int ni = 0; ni < 4; ni++)
                    mma_tf32(acc[mi][ni], afr[mi][0], afr[mi][1], afr[mi][2], afr[mi][3],
                             bfr[ni][0], bfr[ni][1]);
        }
        __syncthreads();
    }

#pragma unroll
    for (int mi = 0; mi < 2; mi++) {
        const int row = m0 + wm + mi * 16 + gid;
#pragma unroll
        for (int ni = 0; ni < 4; ni++) {
            const int col = n0 + wn + ni * 8 + 2 * tig;
            const float2 bb = *(const float2*)&bias[col];
            float2 o0, o1;
            o0.x = acc[mi][ni][0] + bb.x; o0.y = acc[mi][ni][1] + bb.y;
            o1.x = acc[mi][ni][2] + bb.x; o1.y = acc[mi][ni][3] + bb.y;
            if (TF32OUT) {
                o0.x = __uint_as_float(f2tf(o0.x)); o0.y = __uint_as_float(f2tf(o0.y));
                o1.x = __uint_as_float(f2tf(o1.x)); o1.y = __uint_as_float(f2tf(o1.y));
            }
            *(float2*)&C[(size_t)row * N + col]       = o0;
            *(float2*)&C[(size_t)(row + 8) * N + col] = o1;
        }
    }
}

// q/k/v projections batched over blockIdx.z (tf32-rounded outputs)
__global__ __launch_bounds__(128) void qkv_proj_kernel(
    const float* __restrict__ q, const float* __restrict__ k, const float* __restrict__ v,
    const float* __restrict__ Wq, const float* __restrict__ bq,
    const float* __restrict__ Wk, const float* __restrict__ bk,
    const float* __restrict__ Wv, const float* __restrict__ bv,
    float* __restrict__ qp, float* __restrict__ kp, float* __restrict__ vp)
{
    const int z = blockIdx.z;
    const float* A    = (z == 0) ? q  : (z == 1) ? k  : v;
    const float* W    = (z == 0) ? Wq : (z == 1) ? Wk : Wv;
    const float* bias = (z == 0) ? bq : (z == 1) ? bk : bv;
    float*       C    = (z == 0) ? qp : (z == 1) ? kp : vp;
    gemm64_body<true>(A, W, bias, C, DA, DM, blockIdx.y * 64, blockIdx.x * 64);
}

// generic single GEMM (x projection, output projection)
__global__ __launch_bounds__(128) void gemm64_kernel(
    const float* __restrict__ A, const float* __restrict__ W,
    const float* __restrict__ bias, float* __restrict__ C, int N, int K)
{
    gemm64_body<false>(A, W, bias, C, N, K, blockIdx.y * 64, blockIdx.x * 64);
}

// ---------------------------------------------------------------------------
// xdiff bias (fp16 out): bias[b,h,q,k] = 0.5 * sum_f xdiff[b,q,k,f]*x[b,q,h*F+f]
// R13-proven loop structure (one xdiff row per thread, plain cached loads);
// only the store changed: scalar __half (2B) instead of float.
// ---------------------------------------------------------------------------
__global__ __launch_bounds__(256) void xbias_kernel(
    const float* __restrict__ xdiff, const float* __restrict__ xg,
    __half* __restrict__ bias)
{
    __shared__ float xh[H * F];
    const int bq  = blockIdx.x;
    const int b   = bq >> 10;
    const int qi  = bq & 1023;
    const int tid = threadIdx.x;
    if (tid < H * F) xh[tid] = xg[(size_t)bq * (H * F) + tid];
    __syncthreads();
    const float* xd = xdiff + (size_t)bq * S * F;
#pragma unroll
    for (int kt = 0; kt < 4; kt++) {
        const int k = kt * 256 + tid;
        const float4* src = (const float4*)&xd[(size_t)k * F];
        const float4 t0 = src[0], t1 = src[1], t2 = src[2], t3 = src[3];
        const float xv[16] = {t0.x, t0.y, t0.z, t0.w, t1.x, t1.y, t1.z, t1.w,
                              t2.x, t2.y, t2.z, t2.w, t3.x, t3.y, t3.z, t3.w};
#pragma unroll
        for (int h = 0; h < H; h++) {
            float s = 0.0f;
#pragma unroll
            for (int f = 0; f < F; f++) s = fmaf(xv[f], xh[h * F + f], s);
            bias[((size_t)(b * H + h) * S + qi) * S + k] = __float2half(0.5f * s);
        }
    }
}

// ---------------------------------------------------------------------------
// Fused attention, 512 threads / 16 warps, cp.async double-buffered chunks.
// Inputs qp/kp/vp are tf32-pre-rounded -> staging is a pure 16B cp.async copy.
// Bias is fp16 (64MB; mostly L2-resident after xbias).
//   acc = bias (prefetched half2 LDG) + QK^T (Q frags hoisted) -> STS to L
//   softmax(L float) -> attn gmem (float, evict-first) + L (tf32 bits)
//   PV: q(2) x d-half(2x32col) x ks-quarter(4) split; 4-way partial reduce.
//   V chunks 0/1 prefetched during QK tail + softmax.
// smem: L 32x1044 + Qs 32x68 + 2 x (128x72 KV buffers) = 216,064 B
// ---------------------------------------------------------------------------
namespace {
constexpr int LSTR = 1044;
constexpr int QSTR = 68;
constexpr int KSTK = 68;   // K-phase layout stride inside buffer
constexpr int KSTV = 72;   // V-phase layout stride
constexpr int BUFW = 128 * KSTV;
constexpr int PSTR = 72;   // partial-reduce scratch stride
constexpr int FATTN_SMEM = (32 * LSTR + 32 * QSTR + 2 * BUFW) * 4;
}

__global__ __launch_bounds__(512) void fattn_kernel(
    const float* __restrict__ qp, const float* __restrict__ kp,
    const float* __restrict__ vp, const __half* __restrict__ biash,
    float* __restrict__ attn, float* __restrict__ ctx)
{
    extern __shared__ float smem[];
    float*    L  = smem;                               // 32 x LSTR (float / tf32 bits)
    unsigned* Lu = (unsigned*)smem;
    unsigned* Qs = (unsigned*)(smem + 32 * LSTR);      // 32 x QSTR
    unsigned* KV = Qs + 32 * QSTR;                     // 2 x BUFW

    const int tid  = threadIdx.x;
    const int warp = tid >> 5;          // 0..15
    const int lane = tid & 31;
    const int gid  = lane >> 2;
    const int tig  = lane & 3;

    const int bh = blockIdx.y;           // b*H + h
    const int b  = bh >> 3;
    const int h  = bh & 7;
    const int q0 = blockIdx.x * 32;

    const size_t bh_row0 = ((size_t)bh * S + q0) * S;

    const float* Kb = kp + (size_t)b * S * DA + h * 64;
    const float* Vb = vp + (size_t)b * S * DA + h * 64;
    // bias tile as half2 rows: [q][k/2]
    const __half2* Bq = (const __half2*)(biash + (size_t)bh * S * S) + (size_t)q0 * (S / 2);

    // ---- issue cp.async for K chunk 0 ----
#pragma unroll
    for (int p = 0; p < 4; p++) {
        const int i = tid + p * 512;
        cp16(&KV[(i >> 4) * KSTK + (i & 15) * 4], &Kb[(size_t)(i >> 4) * DA + (i & 15) * 4]);
    }
    CP_COMMIT();

    // ---- Q tile -> Qs (x0.125 exact; values already tf32-rounded) ----
    {
        const int row = tid >> 4;
        const int c4  = (tid & 15) * 4;
        const float4 v = *(const float4*)&qp[(size_t)(b * S + q0 + row) * DA + h * 64 + c4];
        unsigned* p = &Qs[row * QSTR + c4];
        p[0] = __float_as_uint(v.x * 0.125f); p[1] = __float_as_uint(v.y * 0.125f);
        p[2] = __float_as_uint(v.z * 0.125f); p[3] = __float_as_uint(v.w * 0.125f);
    }

    // ---- prefetch bias for chunk 0 (half2: one pair per row-group) ----
    const int cidx = warp * 4 + tig;           // half2 index of this warp's col pair
    __half2 bp[2][2];
#pragma unroll
    for (int mi = 0; mi < 2; mi++) {
        const int row = mi * 16 + gid;
        bp[mi][0] = Bq[(size_t)row * (S / 2) + cidx];
        bp[mi][1] = Bq[(size_t)(row + 8) * (S / 2) + cidx];
    }
    CP_WAIT0();
    __syncthreads();

    // ---- hoist Q fragments into registers ----
    unsigned qa[2][8][4];
#pragma unroll
    for (int mi = 0; mi < 2; mi++) {
        const int mr = mi * 16 + gid;
#pragma unroll
        for (int ks = 0; ks < 8; ks++) {
            qa[mi][ks][0] = Qs[mr * QSTR + ks * 8 + tig];
            qa[mi][ks][1] = Qs[(mr + 8) * QSTR + ks * 8 + tig];
            qa[mi][ks][2] = Qs[mr * QSTR + ks * 8 + tig + 4];
            qa[mi][ks][3] = Qs[(mr + 8) * QSTR + ks * 8 + tig + 4];
        }
    }

    const int colw = warp * 8 + tig * 2;       // this warp's 8 cols within a chunk

    // ---- QK^T: acc = bias + QK; result stored once to L ----
    for (int kt = 0; kt < 8; kt++) {
        const unsigned* cur = KV + (kt & 1) * BUFW;

        if (kt < 7) {
            unsigned* nxt = KV + ((kt + 1) & 1) * BUFW;
            const int kbase = (kt + 1) * 128;
#pragma unroll
            for (int p = 0; p < 4; p++) {
                const int i = tid + p * 512;
                cp16(&nxt[(i >> 4) * KSTK + (i & 15) * 4],
                     &Kb[(size_t)(kbase + (i >> 4)) * DA + (i & 15) * 4]);
            }
            CP_COMMIT();
        } else {
            // last K chunk: prefetch V chunk 0 into the other buffer (buf0)
            unsigned* nxt = KV;    // buffer 0
#pragma unroll
            for (int p = 0; p < 4; p++) {
                const int i = tid + p * 512;
                cp16(&nxt[(i >> 4) * KSTV + (i & 15) * 4],
                     &Vb[(size_t)(i >> 4) * DA + (i & 15) * 4]);
            }
            CP_COMMIT();
        }

        float acc[2][4];
#pragma unroll
        for (int mi = 0; mi < 2; mi++) {
            const float2 t0 = __half22float2(bp[mi][0]);
            const float2 t1 = __half22float2(bp[mi][1]);
            acc[mi][0] = t0.x; acc[mi][1] = t0.y; acc[mi][2] = t1.x; acc[mi][3] = t1.y;
        }

        // prefetch bias for next chunk (overlaps mma loop)
        if (kt < 7) {
            const int nci = (kt + 1) * 64 + cidx;
#pragma unroll
            for (int mi = 0; mi < 2; mi++) {
                const int row = mi * 16 + gid;
                bp[mi][0] = Bq[(size_t)row * (S / 2) + nci];
                bp[mi][1] = Bq[(size_t)(row + 8) * (S / 2) + nci];
            }
        }

#pragma unroll
        for (int ks = 0; ks < 8; ks++) {
            const int nc = warp * 8 + gid;
            const unsigned b0 = cur[nc * KSTK + ks * 8 + tig];
            const unsigned b1 = cur[nc * KSTK + ks * 8 + tig + 4];
            mma_tf32(acc[0], qa[0][ks][0], qa[0][ks][1], qa[0][ks][2], qa[0][ks][3], b0, b1);
            mma_tf32(acc[1], qa[1][ks][0], qa[1][ks][1], qa[1][ks][2], qa[1][ks][3], b0, b1);
        }

        // store logits tile (single write, no RMW)
        const int colb = kt * 128 + colw;
#pragma unroll
        for (int mi = 0; mi < 2; mi++) {
            const int row = mi * 16 + gid;
            *(float2*)&L[row * LSTR + colb]       = make_float2(acc[mi][0], acc[mi][1]);
            *(float2*)&L[(row + 8) * LSTR + colb] = make_float2(acc[mi][2], acc[mi][3]);
        }
        if (kt < 7) CP_WAIT0();
        __syncthreads();
    }

    // ---- issue cp.async for V chunk 1 (buf1 free now; overlaps softmax) ----
    {
        unsigned* nxt = KV + BUFW;   // buffer 1
#pragma unroll
        for (int p = 0; p < 4; p++) {
            const int i = tid + p * 512;
            cp16(&nxt[(i >> 4) * KSTV + (i & 15) * 4],
                 &Vb[(size_t)(128 + (i >> 4)) * DA + (i & 15) * 4]);
        }
        CP_COMMIT();
    }

    // ---- softmax (warp per 2 rows): attn gmem (float, evict-first) + L (tf32) ----
#pragma unroll
    for (int r = 0; r < 2; r++) {
        const int row = warp * 2 + r;
        float* Lr = &L[row * LSTR];
        float4 v[8];
        float m = -1e30f;
#pragma unroll
        for (int c = 0; c < 8; c++) {
            v[c] = *(float4*)&Lr[c * 128 + lane * 4];
            m = fmaxf(m, fmaxf(fmaxf(v[c].x, v[c].y), fmaxf(v[c].z, v[c].w)));
        }
#pragma unroll
        for (int o = 16; o; o >>= 1) m = fmaxf(m, __shfl_xor_sync(0xffffffffu, m, o));
        float s = 0.0f;
#pragma unroll
        for (int c = 0; c < 8; c++) {
            v[c].x = __expf(v[c].x - m); v[c].y = __expf(v[c].y - m);
            v[c].z = __expf(v[c].z - m); v[c].w = __expf(v[c].w - m);
            s += v[c].x + v[c].y + v[c].z + v[c].w;
        }
#pragma unroll
        for (int o = 16; o; o >>= 1) s += __shfl_xor_sync(0xffffffffu, s, o);
        const float inv = 1.0f / s;
        float* Ar = attn + bh_row0 + (size_t)row * S;
#pragma unroll
        for (int c = 0; c < 8; c++) {
            v[c].x *= inv; v[c].y *= inv; v[c].z *= inv; v[c].w *= inv;
            __stcs((float4*)&Ar[c * 128 + lane * 4], v[c]);
            uint4 u;
            u.x = f2tf(v[c].x); u.y = f2tf(v[c].y);
            u.z = f2tf(v[c].z); u.w = f2tf(v[c].w);
            *(uint4*)&Lu[row * LSTR + c * 128 + lane * 4] = u;
        }
    }
    CP_WAIT0();
    __syncthreads();

    // ---- PV: ctx tile [32,64] = L @ V ----
    // warp = (wg: ks-quarter) x (mi: q half) x (wn: d half of 32 cols)
    const int wg  = warp >> 2;          // 0..3: which quarter of each chunk's k8-steps
    const int sub = warp & 3;
    const int mi  = sub & 1;
    const int wn  = (sub >> 1) * 32;    // 32 d-cols per warp (4 mma per A-frag)
    const int row = mi * 16 + gid;
    float pacc[4][4] = {};
    for (int kt = 0; kt < 8; kt++) {
        const unsigned* cur = KV + (kt & 1) * BUFW;
        if (kt >= 1 && kt < 7) {
            unsigned* nxt = KV + ((kt + 1) & 1) * BUFW;
            const int kbase = (kt + 1) * 128;
#pragma unroll
            for (int p = 0; p < 4; p++) {
                const int i = tid + p * 512;
                cp16(&nxt[(i >> 4) * KSTV + (i & 15) * 4],
                     &Vb[(size_t)(kbase + (i >> 4)) * DA + (i & 15) * 4]);
            }
            CP_COMMIT();
        }

#pragma unroll
        for (int ks = 0; ks < 4; ks++) {
            const int ksc = wg * 4 + ks;              // 0..15 k8-steps of this chunk
            const int kk  = kt * 128 + ksc * 8;
            const unsigned a0 = Lu[row * LSTR + kk + tig];
            const unsigned a1 = Lu[(row + 8) * LSTR + kk + tig];
            const unsigned a2 = Lu[row * LSTR + kk + tig + 4];
            const unsigned a3 = Lu[(row + 8) * LSTR + kk + tig + 4];
#pragma unroll
            for (int ni = 0; ni < 4; ni++) {
                const unsigned b0 = cur[(ksc * 8 + tig) * KSTV + wn + ni * 8 + gid];
                const unsigned b1 = cur[(ksc * 8 + tig + 4) * KSTV + wn + ni * 8 + gid];
                mma_tf32(pacc[ni], a0, a1, a2, a3, b0, b1);
            }
        }
        if (kt < 7) CP_WAIT0();
        __syncthreads();
    }

    // ---- 4-way partial reduction through freed KV smem, then store ctx ----
    float* Pp = (float*)KV;             // scratch: 3 regions of 32 x PSTR
    if (wg != 0) {
        const int base = (wg - 1) * (32 * PSTR);
#pragma unroll
        for (int ni = 0; ni < 4; ni++) {
            const int col = wn + ni * 8 + tig * 2;
            *(float2*)&Pp[base + row * PSTR + col]       = make_float2(pacc[ni][0], pacc[ni][1]);
            *(float2*)&Pp[base + (row + 8) * PSTR + col] = make_float2(pacc[ni][2], pacc[ni][3]);
        }
    }
    __syncthreads();
    if (wg == 0) {
        const int grow = b * S + q0 + row;
#pragma unroll
        for (int ni = 0; ni < 4; ni++) {
            const int col = wn + ni * 8 + tig * 2;
            float2 o0 = make_float2(pacc[ni][0], pacc[ni][1]);
            float2 o1 = make_float2(pacc[ni][2], pacc[ni][3]);
#pragma unroll
            for (int r = 0; r < 3; r++) {
                const int base = r * (32 * PSTR);
                const float2 p0 = *(const float2*)&Pp[base + row * PSTR + col];
                const float2 p1 = *(const float2*)&Pp[base + (row + 8) * PSTR + col];
                o0.x += p0.x; o0.y += p0.y;
                o1.x += p1.x; o1.y += p1.y;
            }
            *(float2*)&ctx[(size_t)grow * DA + h * 64 + col]       = o0;
            *(float2*)&ctx[(size_t)(grow + 8) * DA + h * 64 + col] = o1;
        }
    }
}

// ---------------------------------------------------------------------------
extern "C" void kernel_launch(void* const* d_in, const int* in_sizes, int n_in,
                              void* d_out, int out_size)
{
    const float* q     = (const float*)d_in[0];
    const float* k     = (const float*)d_in[1];
    const float* v     = (const float*)d_in[2];
    const float* xdiff = (const float*)d_in[3];
    const float* Wq    = (const float*)d_in[4];
    const float* bq    = (const float*)d_in[5];
    const float* Wk    = (const float*)d_in[6];
    const float* bk    = (const float*)d_in[7];
    const float* Wv    = (const float*)d_in[8];
    const float* bv    = (const float*)d_in[9];
    const float* Wx    = (const float*)d_in[10];
    const float* bx    = (const float*)d_in[11];
    const float* Wo    = (const float*)d_in[12];
    const float* bo    = (const float*)d_in[13];

    float* out_final = (float*)d_out;                       // [B,S,DM]
    float* attn      = out_final + (size_t)B * S * DM;      // [B,H,S,S]

    float *qp, *kp, *vp, *xg, *ctx;
    __half* biasb;
    cudaGetSymbolAddress((void**)&qp,    g_qp);
    cudaGetSymbolAddress((void**)&kp,    g_kp);
    cudaGetSymbolAddress((void**)&vp,    g_vp);
    cudaGetSymbolAddress((void**)&xg,    g_x);
    cudaGetSymbolAddress((void**)&ctx,   g_ctx);
    cudaGetSymbolAddress((void**)&biasb, g_bias);

    cudaFuncSetAttribute(fattn_kernel, cudaFuncAttributeMaxDynamicSharedMemorySize,
                         FATTN_SMEM);

    // 1. q/k/v projections, one batched launch (tf32-rounded outputs)
    qkv_proj_kernel<<<dim3(DA / 64, (B * S) / 64, 3), 128>>>(
        q, k, v, Wq, bq, Wk, bk, Wv, bv, qp, kp, vp);

    // 2. x = qp @ Wx + bx
    gemm64_kernel<<<dim3((H * F) / 64, (B * S) / 64), 128>>>(qp, Wx, bx, xg, H * F, DA);

    // 3. xdiff relative bias -> fp16 bias buffer
    xbias_kernel<<<B * S, 256>>>(xdiff, xg, biasb);

    // 4. fused: logits = bias + QK^T, softmax, attn out, PV -> ctx
    fattn_kernel<<<dim3(S / 32, B * H), 512, FATTN_SMEM>>>(qp, kp, vp, biasb, attn, ctx);

    // 5. output = ctx @ Wo + bo
    gemm64_kernel<<<dim3(DM / 64, (B * S) / 64), 128>>>(ctx, Wo, bo, out_final, DM, DA);
}

// round 16
// speedup vs baseline: 1.1737x; 1.0080x over previous
#include <cuda_runtime.h>
#include <cuda_fp16.h>

// Problem constants
namespace {
constexpr int B  = 4;
constexpr int S  = 1024;
constexpr int DM = 512;
constexpr int DA = 512;
constexpr int H  = 8;
constexpr int F  = 16;
}

// Scratch (static device globals -- no allocations allowed)
__device__ float  g_qp [B * S * DA];              // 8 MB fp32 (for x-gemm)
__device__ __half g_qh [B * S * DA];              // 4 MB fp16, pre-scaled 0.125
__device__ __half g_kh [B * S * DA];              // 4 MB fp16
__device__ __half g_vt [B * H * 64 * S];          // 4 MB fp16, [b][h][d][key]
__device__ float  g_x  [B * S * H * F];           // 2 MB
__device__ float  g_ctx[B * S * DA];              // 8 MB
__device__ __half g_bias[(size_t)B * H * S * S];  // 64 MB fp16 logit bias

// ---------------------------------------------------------------------------
// helpers
// ---------------------------------------------------------------------------
__device__ __forceinline__ unsigned f2tf(float f) {
    unsigned u;
    asm("cvt.rna.tf32.f32 %0, %1;" : "=r"(u) : "f"(f));
    return u;
}

__device__ __forceinline__ void mma_tf32(float c[4],
                                         unsigned a0, unsigned a1, unsigned a2, unsigned a3,
                                         unsigned b0, unsigned b1) {
    asm volatile(
        "mma.sync.aligned.m16n8k8.row.col.f32.tf32.tf32.f32 "
        "{%0,%1,%2,%3}, {%4,%5,%6,%7}, {%8,%9}, {%0,%1,%2,%3};"
        : "+f"(c[0]), "+f"(c[1]), "+f"(c[2]), "+f"(c[3])
        : "r"(a0), "r"(a1), "r"(a2), "r"(a3), "r"(b0), "r"(b1));
}

// fp16 m16n8k16 mma, fp32 accumulate
__device__ __forceinline__ void mma_f16(float c[4],
                                        unsigned a0, unsigned a1, unsigned a2, unsigned a3,
                                        unsigned b0, unsigned b1) {
    asm volatile(
        "mma.sync.aligned.m16n8k16.row.col.f32.f16.f16.f32 "
        "{%0,%1,%2,%3}, {%4,%5,%6,%7}, {%8,%9}, {%0,%1,%2,%3};"
        : "+f"(c[0]), "+f"(c[1]), "+f"(c[2]), "+f"(c[3])
        : "r"(a0), "r"(a1), "r"(a2), "r"(a3), "r"(b0), "r"(b1));
}

__device__ __forceinline__ void cp16(void* dst_smem, const void* src_gmem) {
    const unsigned s = (unsigned)__cvta_generic_to_shared(dst_smem);
    asm volatile("cp.async.cg.shared.global [%0], [%1], 16;" :: "r"(s), "l"(src_gmem));
}
#define CP_COMMIT() asm volatile("cp.async.commit_group;")
#define CP_WAIT0()  asm volatile("cp.async.wait_group 0;" ::: "memory")

// ---------------------------------------------------------------------------
// 64x64-tile tf32 GEMM body, templated epilogue:
//   MODE 0: plain fp32 C                        (x-gemm, out-proj)
//   MODE 1: fp32 C  +  fp16 Ch scaled by 0.125  (q projection)
//   MODE 2: fp16 Ch                             (k projection)
//   MODE 3: fp16 Ch transposed [b][h][d][key]   (v projection)
// ---------------------------------------------------------------------------
template <int MODE>
__device__ __forceinline__ void gemm64_body(
    const float* __restrict__ A, const float* __restrict__ W,
    const float* __restrict__ bias, float* __restrict__ C,
    __half* __restrict__ Ch, int N, int K, int m0, int n0)
{
    constexpr int AS = 20;   // As[m][k], 16+4
    constexpr int BS = 72;   // Bs[k][n], 64+8
    __shared__ unsigned As[64 * AS];
    __shared__ unsigned Bs[16 * BS];

    const int tid  = threadIdx.x;
    const int warp = tid >> 5;
    const int lane = tid & 31;
    const int gid  = lane >> 2;
    const int tig  = lane & 3;
    const int wm   = (warp & 1) * 32;
    const int wn   = (warp >> 1) * 32;

    float4 ra[2], rb[2];
#pragma unroll
    for (int p = 0; p < 2; p++) {
        const int ia = tid + p * 128;
        ra[p] = *(const float4*)&A[(size_t)(m0 + (ia >> 2)) * K + (ia & 3) * 4];
        const int ib = tid + p * 128;
        rb[p] = *(const float4*)&W[(size_t)(ib >> 4) * N + n0 + (ib & 15) * 4];
    }

    float acc[2][4][4] = {};

    for (int k0 = 0; k0 < K; k0 += 16) {
#pragma unroll
        for (int p = 0; p < 2; p++) {
            const int ia = tid + p * 128;
            unsigned* pa = &As[(ia >> 2) * AS + (ia & 3) * 4];
            pa[0] = f2tf(ra[p].x); pa[1] = f2tf(ra[p].y);
            pa[2] = f2tf(ra[p].z); pa[3] = f2tf(ra[p].w);
            const int ib = tid + p * 128;
            unsigned* pb = &Bs[(ib >> 4) * BS + (ib & 15) * 4];
            pb[0] = f2tf(rb[p].x); pb[1] = f2tf(rb[p].y);
            pb[2] = f2tf(rb[p].z); pb[3] = f2tf(rb[p].w);
        }
        __syncthreads();
        if (k0 + 16 < K) {
#pragma unroll
            for (int p = 0; p < 2; p++) {
                const int ia = tid + p * 128;
                ra[p] = *(const float4*)&A[(size_t)(m0 + (ia >> 2)) * K + k0 + 16 + (ia & 3) * 4];
                const int ib = tid + p * 128;
                rb[p] = *(const float4*)&W[(size_t)(k0 + 16 + (ib >> 4)) * N + n0 + (ib & 15) * 4];
            }
        }
#pragma unroll
        for (int ks = 0; ks < 2; ks++) {
            unsigned afr[2][4];
#pragma unroll
            for (int mi = 0; mi < 2; mi++) {
                const int mr = wm + mi * 16 + gid;
                afr[mi][0] = As[mr * AS + ks * 8 + tig];
                afr[mi][1] = As[(mr + 8) * AS + ks * 8 + tig];
                afr[mi][2] = As[mr * AS + ks * 8 + tig + 4];
                afr[mi][3] = As[(mr + 8) * AS + ks * 8 + tig + 4];
            }
            unsigned bfr[4][2];
#pragma unroll
            for (int ni = 0; ni < 4; ni++) {
                const int nc = wn + ni * 8 + gid;
                bfr[ni][0] = Bs[(ks * 8 + tig) * BS + nc];
                bfr[ni][1] = Bs[(ks * 8 + tig + 4) * BS + nc];
            }
#pragma unroll
            for (int mi = 0; mi < 2; mi++)
#pragma unroll
                for (int ni = 0; ni < 4; ni++)
                    mma_tf32(acc[mi][ni], afr[mi][0], afr[mi][1], afr[mi][2], afr[mi][3],
                             bfr[ni][0], bfr[ni][1]);
        }
        __syncthreads();
    }

#pragma unroll
    for (int mi = 0; mi < 2; mi++) {
        const int row = m0 + wm + mi * 16 + gid;
#pragma unroll
        for (int ni = 0; ni < 4; ni++) {
            const int col = n0 + wn + ni * 8 + 2 * tig;
            const float2 bb = *(const float2*)&bias[col];
            float2 o0, o1;
            o0.x = acc[mi][ni][0] + bb.x; o0.y = acc[mi][ni][1] + bb.y;
            o1.x = acc[mi][ni][2] + bb.x; o1.y = acc[mi][ni][3] + bb.y;
            if constexpr (MODE == 0 || MODE == 1) {
                *(float2*)&C[(size_t)row * N + col]       = o0;
                *(float2*)&C[(size_t)(row + 8) * N + col] = o1;
            }
            if constexpr (MODE == 1) {
                *(__half2*)&Ch[(size_t)row * N + col] =
                    __floats2half2_rn(o0.x * 0.125f, o0.y * 0.125f);
                *(__half2*)&Ch[(size_t)(row + 8) * N + col] =
                    __floats2half2_rn(o1.x * 0.125f, o1.y * 0.125f);
            }
            if constexpr (MODE == 2) {
                *(__half2*)&Ch[(size_t)row * N + col]       = __floats2half2_rn(o0.x, o0.y);
                *(__half2*)&Ch[(size_t)(row + 8) * N + col] = __floats2half2_rn(o1.x, o1.y);
            }
            if constexpr (MODE == 3) {
                // vt[((b*H + h)*64 + d)*1024 + key]; rows row/row+8 share b.
                const int bb_ = row >> 10;
                const int key = row & 1023;
                const int hh  = col >> 6;
                const int d0  = col & 63;
                __half* base = Ch + ((size_t)(bb_ * H + hh) * 64) * 1024;
                base[(size_t)d0 * 1024 + key]           = __float2half(o0.x);
                base[(size_t)(d0 + 1) * 1024 + key]     = __float2half(o0.y);
                base[(size_t)d0 * 1024 + key + 8]       = __float2half(o1.x);
                base[(size_t)(d0 + 1) * 1024 + key + 8] = __float2half(o1.y);
            }
        }
    }
}

// q/k/v projections batched over blockIdx.z
__global__ __launch_bounds__(128) void qkv_proj_kernel(
    const float* __restrict__ q, const float* __restrict__ k, const float* __restrict__ v,
    const float* __restrict__ Wq, const float* __restrict__ bq,
    const float* __restrict__ Wk, const float* __restrict__ bk,
    const float* __restrict__ Wv, const float* __restrict__ bv,
    float* __restrict__ qp, __half* __restrict__ qh,
    __half* __restrict__ kh, __half* __restrict__ vt)
{
    const int z = blockIdx.z;
    const int m0 = blockIdx.y * 64, n0 = blockIdx.x * 64;
    if (z == 0)      gemm64_body<1>(q, Wq, bq, qp,      qh, DA, DM, m0, n0);
    else if (z == 1) gemm64_body<2>(k, Wk, bk, nullptr, kh, DA, DM, m0, n0);
    else             gemm64_body<3>(v, Wv, bv, nullptr, vt, DA, DM, m0, n0);
}

// generic single GEMM (x projection, output projection)
__global__ __launch_bounds__(128) void gemm64_kernel(
    const float* __restrict__ A, const float* __restrict__ W,
    const float* __restrict__ bias, float* __restrict__ C, int N, int K)
{
    gemm64_body<0>(A, W, bias, C, nullptr, N, K, blockIdx.y * 64, blockIdx.x * 64);
}

// ---------------------------------------------------------------------------
// xdiff bias (fp16 out): bias[b,h,q,k] = 0.5 * sum_f xdiff[b,q,k,f]*x[b,q,h*F+f]
// ---------------------------------------------------------------------------
__global__ __launch_bounds__(256) void xbias_kernel(
    const float* __restrict__ xdiff, const float* __restrict__ xg,
    __half* __restrict__ bias)
{
    __shared__ float xh[H * F];
    const int bq  = blockIdx.x;
    const int b   = bq >> 10;
    const int qi  = bq & 1023;
    const int tid = threadIdx.x;
    if (tid < H * F) xh[tid] = xg[(size_t)bq * (H * F) + tid];
    __syncthreads();
    const float* xd = xdiff + (size_t)bq * S * F;
#pragma unroll
    for (int kt = 0; kt < 4; kt++) {
        const int k = kt * 256 + tid;
        const float4* src = (const float4*)&xd[(size_t)k * F];
        const float4 t0 = src[0], t1 = src[1], t2 = src[2], t3 = src[3];
        const float xv[16] = {t0.x, t0.y, t0.z, t0.w, t1.x, t1.y, t1.z, t1.w,
                              t2.x, t2.y, t2.z, t2.w, t3.x, t3.y, t3.z, t3.w};
#pragma unroll
        for (int h = 0; h < H; h++) {
            float s = 0.0f;
#pragma unroll
            for (int f = 0; f < F; f++) s = fmaf(xv[f], xh[h * F + f], s);
            bias[((size_t)(b * H + h) * S + qi) * S + k] = __float2half(0.5f * s);
        }
    }
}

// ---------------------------------------------------------------------------
// Fused attention, fp16 m16n8k16 tensor path, 512 threads / 16 warps,
// cp.async double-buffered 128-key chunks.
//   acc(f32) = bias(fp16 LDG, prefetched) + Q(fp16 regs) K^T(fp16 smem)
//   -> L f32 -> softmax f32 -> attn gmem f32 + probs half2 in-place in L
//   -> PV fp16 mma from L(half2) x V^T(fp16 smem, staged from g_vt) -> ctx f32
// smem: L 32x1044 f32 + Qs 32x36 w + 2 x (128x36 w) = 175,104 B
// ---------------------------------------------------------------------------
namespace {
constexpr int LSTR = 1044;   // f32 words per L row (logits); probs use same rows
constexpr int QW   = 36;     // Q smem row stride (b32 words: 32 data + 4 pad)
constexpr int KW   = 36;     // K chunk row stride (rows=key, 32 words of d)
constexpr int VW   = 68;     // V chunk row stride (rows=d, 64 words of key)
constexpr int BUFW = 128 * KW;   // 4608 words; V chunk (64*68=4352) also fits
constexpr int PSTR = 72;     // partial-reduce scratch stride
constexpr int FATTN_SMEM = (32 * LSTR + 32 * QW + 2 * BUFW) * 4;
}

__global__ __launch_bounds__(512) void fattn_kernel(
    const __half* __restrict__ qh, const __half* __restrict__ kh,
    const __half* __restrict__ vt, const __half* __restrict__ biash,
    float* __restrict__ attn, float* __restrict__ ctx)
{
    extern __shared__ float smem[];
    float*    L  = smem;                               // 32 x LSTR
    unsigned* Lu = (unsigned*)smem;
    unsigned* Qs = (unsigned*)(smem + 32 * LSTR);      // 32 x QW
    unsigned* KV = Qs + 32 * QW;                       // 2 x BUFW

    const int tid  = threadIdx.x;
    const int warp = tid >> 5;          // 0..15
    const int lane = tid & 31;
    const int gid  = lane >> 2;
    const int tig  = lane & 3;

    const int bh = blockIdx.y;           // b*H + h
    const int b  = bh >> 3;
    const int h  = bh & 7;
    const int q0 = blockIdx.x * 32;

    const size_t bh_row0 = ((size_t)bh * S + q0) * S;

    const __half* Kb = kh + (size_t)b * S * DA + h * 64;          // + key*DA
    const __half* Vt = vt + ((size_t)bh * 64) * 1024;             // + d*1024 + key
    const __half* Qb = qh + ((size_t)(b * S + q0)) * DA + h * 64; // + row*DA
    const __half2* Bq = (const __half2*)(biash + (size_t)bh * S * S) + (size_t)q0 * (S / 2);

    // ---- issue cp.async for K chunk 0: 128 rows x 8 x 16B ----
#pragma unroll
    for (int p = 0; p < 2; p++) {
        const int i = tid + p * 512;               // 0..1023
        const int r = i >> 3, j = i & 7;
        cp16(&KV[r * KW + j * 4], Kb + (size_t)r * DA + j * 8);
    }
    CP_COMMIT();

    // ---- Q tile -> Qs (fp16, already scaled): 32 rows x 8 x 16B ----
    if (tid < 256) {
        const int row = tid >> 3, j = tid & 7;
        *(uint4*)&Qs[row * QW + j * 4] = *(const uint4*)(Qb + (size_t)row * DA + j * 8);
    }

    // ---- prefetch bias for chunk 0 ----
    const int cidx = warp * 4 + tig;           // half2 idx of this warp's col pair
    __half2 bp[2][2];
#pragma unroll
    for (int mi = 0; mi < 2; mi++) {
        const int row = mi * 16 + gid;
        bp[mi][0] = Bq[(size_t)row * (S / 2) + cidx];
        bp[mi][1] = Bq[(size_t)(row + 8) * (S / 2) + cidx];
    }
    CP_WAIT0();
    __syncthreads();

    // ---- hoist Q fragments (m16n8k16 A) into registers: 16 regs ----
    unsigned qa[2][4][4];
#pragma unroll
    for (int mi = 0; mi < 2; mi++) {
        const int mr = mi * 16 + gid;
#pragma unroll
        for (int ks = 0; ks < 4; ks++) {
            qa[mi][ks][0] = Qs[mr * QW + ks * 8 + tig];
            qa[mi][ks][1] = Qs[(mr + 8) * QW + ks * 8 + tig];
            qa[mi][ks][2] = Qs[mr * QW + ks * 8 + tig + 4];
            qa[mi][ks][3] = Qs[(mr + 8) * QW + ks * 8 + tig + 4];
        }
    }

    const int colw = warp * 8 + tig * 2;       // this warp's cols within a chunk

    // ---- QK^T: acc = bias + QK; result stored once to L (f32) ----
    for (int kt = 0; kt < 8; kt++) {
        const unsigned* cur = KV + (kt & 1) * BUFW;

        if (kt < 7) {
            unsigned* nxt = KV + ((kt + 1) & 1) * BUFW;
            const int kbase = (kt + 1) * 128;
#pragma unroll
            for (int p = 0; p < 2; p++) {
                const int i = tid + p * 512;
                const int r = i >> 3, j = i & 7;
                cp16(&nxt[r * KW + j * 4], Kb + (size_t)(kbase + r) * DA + j * 8);
            }
            CP_COMMIT();
        } else {
            // last K chunk: prefetch V chunk 0 into buf0 (V layout: 64 d-rows x 16 x 16B)
            unsigned* nxt = KV;
#pragma unroll
            for (int p = 0; p < 2; p++) {
                const int i = tid + p * 512;
                const int d = i >> 4, j = i & 15;
                cp16(&nxt[d * VW + j * 4], Vt + (size_t)d * 1024 + j * 8);
            }
            CP_COMMIT();
        }

        float acc[2][4];
#pragma unroll
        for (int mi = 0; mi < 2; mi++) {
            const float2 t0 = __half22float2(bp[mi][0]);
            const float2 t1 = __half22float2(bp[mi][1]);
            acc[mi][0] = t0.x; acc[mi][1] = t0.y; acc[mi][2] = t1.x; acc[mi][3] = t1.y;
        }

        if (kt < 7) {
            const int nci = (kt + 1) * 64 + cidx;
#pragma unroll
            for (int mi = 0; mi < 2; mi++) {
                const int row = mi * 16 + gid;
                bp[mi][0] = Bq[(size_t)row * (S / 2) + nci];
                bp[mi][1] = Bq[(size_t)(row + 8) * (S / 2) + nci];
            }
        }

        const int nc = warp * 8 + gid;      // this warp's key within the chunk
#pragma unroll
        for (int ks = 0; ks < 4; ks++) {    // 4 x k16 = 64 d
            const unsigned b0 = cur[nc * KW + ks * 8 + tig];
            const unsigned b1 = cur[nc * KW + ks * 8 + tig + 4];
            mma_f16(acc[0], qa[0][ks][0], qa[0][ks][1], qa[0][ks][2], qa[0][ks][3], b0, b1);
            mma_f16(acc[1], qa[1][ks][0], qa[1][ks][1], qa[1][ks][2], qa[1][ks][3], b0, b1);
        }

        const int colb = kt * 128 + colw;
#pragma unroll
        for (int mi = 0; mi < 2; mi++) {
            const int row = mi * 16 + gid;
            *(float2*)&L[row * LSTR + colb]       = make_float2(acc[mi][0], acc[mi][1]);
            *(float2*)&L[(row + 8) * LSTR + colb] = make_float2(acc[mi][2], acc[mi][3]);
        }
        if (kt < 7) CP_WAIT0();
        __syncthreads();
    }

    // ---- issue cp.async for V chunk 1 into buf1 (overlaps softmax) ----
    {
        unsigned* nxt = KV + BUFW;
#pragma unroll
        for (int p = 0; p < 2; p++) {
            const int i = tid + p * 512;
            const int d = i >> 4, j = i & 15;
            cp16(&nxt[d * VW + j * 4], Vt + (size_t)d * 1024 + 128 + j * 8);
        }
        CP_COMMIT();
    }

    // ---- softmax (warp per 2 rows): attn gmem f32 + probs half2 in-place in L ----
#pragma unroll
    for (int r = 0; r < 2; r++) {
        const int row = warp * 2 + r;
        float* Lr = &L[row * LSTR];
        float4 v[8];
        float m = -1e30f;
#pragma unroll
        for (int c = 0; c < 8; c++) {
            v[c] = *(float4*)&Lr[c * 128 + lane * 4];
            m = fmaxf(m, fmaxf(fmaxf(v[c].x, v[c].y), fmaxf(v[c].z, v[c].w)));
        }
#pragma unroll
        for (int o = 16; o; o >>= 1) m = fmaxf(m, __shfl_xor_sync(0xffffffffu, m, o));
        float s = 0.0f;
#pragma unroll
        for (int c = 0; c < 8; c++) {
            v[c].x = __expf(v[c].x - m); v[c].y = __expf(v[c].y - m);
            v[c].z = __expf(v[c].z - m); v[c].w = __expf(v[c].w - m);
            s += v[c].x + v[c].y + v[c].z + v[c].w;
        }
#pragma unroll
        for (int o = 16; o; o >>= 1) s += __shfl_xor_sync(0xffffffffu, s, o);
        const float inv = 1.0f / s;
        float* Ar = attn + bh_row0 + (size_t)row * S;
#pragma unroll
        for (int c = 0; c < 8; c++) {
            v[c].x *= inv; v[c].y *= inv; v[c].z *= inv; v[c].w *= inv;
            __stcs((float4*)&Ar[c * 128 + lane * 4], v[c]);
            const __half2 h0 = __floats2half2_rn(v[c].x, v[c].y);
            const __half2 h1 = __floats2half2_rn(v[c].z, v[c].w);
            uint2 u;
            u.x = *(const unsigned*)&h0;
            u.y = *(const unsigned*)&h1;
            *(uint2*)&Lu[row * LSTR + c * 64 + lane * 2] = u;
        }
    }
    CP_WAIT0();
    __syncthreads();

    // ---- PV: ctx tile [32,64] = P(half2 in L) @ V^T(fp16 smem) ----
    // warp = (wg: k16-step pair) x (mi: q half) x (wn: 32 d-cols)
    const int wg  = warp >> 2;          // 0..3
    const int sub = warp & 3;
    const int mi  = sub & 1;
    const int wn  = (sub >> 1) * 32;
    const int row = mi * 16 + gid;
    float pacc[4][4] = {};
    for (int kt = 0; kt < 8; kt++) {
        const unsigned* cur = KV + (kt & 1) * BUFW;
        if (kt >= 1 && kt < 7) {
            unsigned* nxt = KV + ((kt + 1) & 1) * BUFW;
            const int kbase = (kt + 1) * 128;
#pragma unroll
            for (int p = 0; p < 2; p++) {
                const int i = tid + p * 512;
                const int d = i >> 4, j = i & 15;
                cp16(&nxt[d * VW + j * 4], Vt + (size_t)d * 1024 + kbase + j * 8);
            }
            CP_COMMIT();
        }

#pragma unroll
        for (int ks = 0; ks < 2; ks++) {
            const int ksc = wg * 2 + ks;              // 0..7 k16-steps of this chunk
            const int kkw = kt * 64 + ksc * 8;        // half2-word offset in L row
            const unsigned a0 = Lu[row * LSTR + kkw + tig];
            const unsigned a1 = Lu[(row + 8) * LSTR + kkw + tig];
            const unsigned a2 = Lu[row * LSTR + kkw + tig + 4];
            const unsigned a3 = Lu[(row + 8) * LSTR + kkw + tig + 4];
#pragma unroll
            for (int ni = 0; ni < 4; ni++) {
                const int d = wn + ni * 8 + gid;
                const unsigned b0 = cur[d * VW + ksc * 8 + tig];
                const unsigned b1 = cur[d * VW + ksc * 8 + tig + 4];
                mma_f16(pacc[ni], a0, a1, a2, a3, b0, b1);
            }
        }
        if (kt < 7) CP_WAIT0();
        __syncthreads();
    }

    // ---- 4-way partial reduction through freed KV smem, then store ctx ----
    float* Pp = (float*)KV;             // scratch: 3 regions of 32 x PSTR
    if (wg != 0) {
        const int base = (wg - 1) * (32 * PSTR);
#pragma unroll
        for (int ni = 0; ni < 4; ni++) {
            const int col = wn + ni * 8 + tig * 2;
            *(float2*)&Pp[base + row * PSTR + col]       = make_float2(pacc[ni][0], pacc[ni][1]);
            *(float2*)&Pp[base + (row + 8) * PSTR + col] = make_float2(pacc[ni][2], pacc[ni][3]);
        }
    }
    __syncthreads();
    if (wg == 0) {
        const int grow = b * S + q0 + row;
#pragma unroll
        for (int ni = 0; ni < 4; ni++) {
            const int col = wn + ni * 8 + tig * 2;
            float2 o0 = make_float2(pacc[ni][0], pacc[ni][1]);
            float2 o1 = make_float2(pacc[ni][2], pacc[ni][3]);
#pragma unroll
            for (int r = 0; r < 3; r++) {
                const int base = r * (32 * PSTR);
                const float2 p0 = *(const float2*)&Pp[base + row * PSTR + col];
                const float2 p1 = *(const float2*)&Pp[base + (row + 8) * PSTR + col];
                o0.x += p0.x; o0.y += p0.y;
                o1.x += p1.x; o1.y += p1.y;
            }
            *(float2*)&ctx[(size_t)grow * DA + h * 64 + col]       = o0;
            *(float2*)&ctx[(size_t)(grow + 8) * DA + h * 64 + col] = o1;
        }
    }
}

// ---------------------------------------------------------------------------
extern "C" void kernel_launch(void* const* d_in, const int* in_sizes, int n_in,
                              void* d_out, int out_size)
{
    const float* q     = (const float*)d_in[0];
    const float* k     = (const float*)d_in[1];
    const float* v     = (const float*)d_in[2];
    const float* xdiff = (const float*)d_in[3];
    const float* Wq    = (const float*)d_in[4];
    const float* bq    = (const float*)d_in[5];
    const float* Wk    = (const float*)d_in[6];
    const float* bk    = (const float*)d_in[7];
    const float* Wv    = (const float*)d_in[8];
    const float* bv    = (const float*)d_in[9];
    const float* Wx    = (const float*)d_in[10];
    const float* bx    = (const float*)d_in[11];
    const float* Wo    = (const float*)d_in[12];
    const float* bo    = (const float*)d_in[13];

    float* out_final = (float*)d_out;                       // [B,S,DM]
    float* attn      = out_final + (size_t)B * S * DM;      // [B,H,S,S]

    float *qp, *xg, *ctx;
    __half *qh, *kh, *vt, *biasb;
    cudaGetSymbolAddress((void**)&qp,    g_qp);
    cudaGetSymbolAddress((void**)&qh,    g_qh);
    cudaGetSymbolAddress((void**)&kh,    g_kh);
    cudaGetSymbolAddress((void**)&vt,    g_vt);
    cudaGetSymbolAddress((void**)&xg,    g_x);
    cudaGetSymbolAddress((void**)&ctx,   g_ctx);
    cudaGetSymbolAddress((void**)&biasb, g_bias);

    cudaFuncSetAttribute(fattn_kernel, cudaFuncAttributeMaxDynamicSharedMemorySize,
                         FATTN_SMEM);

    // 1. q/k/v projections (fp16 side outputs; qp fp32 kept for x-gemm)
    qkv_proj_kernel<<<dim3(DA / 64, (B * S) / 64, 3), 128>>>(
        q, k, v, Wq, bq, Wk, bk, Wv, bv, qp, qh, kh, vt);

    // 2. x = qp @ Wx + bx
    gemm64_kernel<<<dim3((H * F) / 64, (B * S) / 64), 128>>>(qp, Wx, bx, xg, H * F, DA);

    // 3. xdiff relative bias -> fp16 bias buffer
    xbias_kernel<<<B * S, 256>>>(xdiff, xg, biasb);

    // 4. fused fp16 attention: logits = bias + QK^T, softmax, attn out, PV -> ctx
    fattn_kernel<<<dim3(S / 32, B * H), 512, FATTN_SMEM>>>(qh, kh, vt, biasb, attn, ctx);

    // 5. output = ctx @ Wo + bo
    gemm64_kernel<<<dim3(DM / 64, (B * S) / 64), 128>>>(ctx, Wo, bo, out_final, DM, DA);
}